// round 16
// baseline (speedup 1.0000x reference)
#include <cuda_runtime.h>
#include <cstdint>

#define BATCH 16
#define NPTS  4096
#define CH    64
#define MCENT 1024
#define KNB   32
#define RAD2  0.04f

typedef unsigned long long u64;

// scratch (allocation-free rule: __device__ globals)
__device__ float    g_pf[BATCH * NPTS * 64];   // 16 MB: W1[:,3:]@feat + b1
__device__ unsigned g_prog[BATCH];             // FPS progress (centroids published)
__device__ unsigned g_pfdone;                  // pf slices completed
__device__ unsigned g_ticket;                  // consumer work queue

// packed f32x2 helpers (sm_100+)
#define PK2(out, lo, hi)  asm("mov.b64 %0, {%1, %2};" : "=l"(out) : "f"(lo), "f"(hi))
#define UPK2(lo, hi, in)  asm("mov.b64 {%0, %1}, %2;" : "=f"(lo), "=f"(hi) : "l"(in))
#define ADD2(o, a, b)     asm("add.rn.f32x2 %0, %1, %2;" : "=l"(o) : "l"(a), "l"(b))
#define MUL2(o, a, b)     asm("mul.rn.f32x2 %0, %1, %2;" : "=l"(o) : "l"(a), "l"(b))
#define FMA2(o, a, b, c)  asm("fma.rn.f32x2 %0, %1, %2, %3;" : "=l"(o) : "l"(a), "l"(b), "l"(c))

#define QBAR(q) asm volatile("bar.sync %0, 128;" :: "r"((q) + 1) : "memory")

__device__ __forceinline__ unsigned ldacq(const unsigned* p) {
    unsigned v; asm volatile("ld.acquire.gpu.global.u32 %0, [%1];" : "=r"(v) : "l"(p)); return v;
}

// bufA addressing: stride 68 floats/row + XOR swizzle of float4 index by (r>>3)&3
__device__ __forceinline__ int aidx(int r, int c4) {
    return r * 68 + (((c4 ^ (r >> 3)) & 3) << 2) + ((c4 >> 2) << 4);
}

__global__ void init_kernel() {
    int t = threadIdx.x;
    if (t < BATCH) g_prog[t] = 0u;
    if (t == BATCH) g_pfdone = 0u;
    if (t == BATCH + 1) g_ticket = 0u;
}

// ---------------------------------------------------------------------------
// Packed-f32x2 8x8 register-tile GEMM (R6-proven) from swizzled bufA.
// ---------------------------------------------------------------------------
template <int WS>
__device__ __forceinline__ void gemm8x8p(const float* __restrict__ A,
                                         const float* __restrict__ W,
                                         int r0, int o0, int sw, u64 (&acc)[8][4]) {
#pragma unroll
    for (int i = 0; i < 8; i++)
#pragma unroll
        for (int j = 0; j < 4; j++) acc[i][j] = 0ull;

#pragma unroll 2
    for (int cc = 0; cc < 64; cc += 4) {
        const int c4  = cc >> 2;
        const int pc4 = ((c4 >> 2) << 4) + (((c4 ^ sw) & 3) << 2);
        float4 a[8];
#pragma unroll
        for (int i = 0; i < 8; i++)
            a[i] = *(const float4*)(A + (r0 + i) * 68 + pc4);
#pragma unroll
        for (int j = 0; j < 4; j++) {
            const float* wrow = W + (cc + j) * WS + o0;
            ulonglong2 wA = *(const ulonglong2*)(wrow);
            ulonglong2 wB = *(const ulonglong2*)(wrow + 4);
#pragma unroll
            for (int i = 0; i < 8; i++) {
                float av = (j == 0) ? a[i].x : (j == 1) ? a[i].y : (j == 2) ? a[i].z : a[i].w;
                u64 ap; PK2(ap, av, av);
                FMA2(acc[i][0], ap, wA.x, acc[i][0]);
                FMA2(acc[i][1], ap, wA.y, acc[i][1]);
                FMA2(acc[i][2], ap, wB.x, acc[i][2]);
                FMA2(acc[i][3], ap, wB.y, acc[i][3]);
            }
        }
    }
}

// smem layout constants (floats) for the worker role
#define SMW_W2   0            // 4096
#define SMW_W3   4096         // 8192
#define SMW_W1P  12288        // 192
#define SMW_S1   12480
#define SMW_BE1  12544
#define SMW_B2   12608
#define SMW_S2   12672
#define SMW_BE2  12736
#define SMW_B3   12800        // 128
#define SMW_S3   12928
#define SMW_BE3  13056
#define SMW_END  13184
#define QSZ      9760         // bufA 8704 + loc 384 + centv 16 + outb 512 + ni 128 + tick 16
#define MEGA_SMEM ((SMW_END + 4 * QSZ) * 4)   // 208,896 B -> 1 block/SM
#define NITEMS   (BATCH * MCENT / 4)          // 4096 work items (4 centroids each)

// ---------------------------------------------------------------------------
// MEGA kernel, ONE wave of 148 blocks:
//   bids [0,16):   FPS, then falls through to the worker loop
//   bids [16,148): workers; the first 128 do a pf slice first
// ---------------------------------------------------------------------------
__global__ void __launch_bounds__(512) mega_kernel(
    const float* __restrict__ pts, const float* __restrict__ feats,
    const float* __restrict__ w1, const float* __restrict__ b1,
    const float* __restrict__ g1, const float* __restrict__ be1,
    const float* __restrict__ w2, const float* __restrict__ b2,
    const float* __restrict__ g2, const float* __restrict__ be2,
    const float* __restrict__ w3, const float* __restrict__ b3,
    const float* __restrict__ g3, const float* __restrict__ be3,
    float* __restrict__ cent_out, float* __restrict__ out) {
    extern __shared__ float sm[];
    const int tid = threadIdx.x;

    if (blockIdx.x < BATCH) {
        // =================== FPS (R6-proven, 512 thr, 8 pts/thr) ===========
        float* spx = sm;
        float* spy = sm + NPTS;
        float* spz = sm + 2 * NPTS;
        unsigned* swd = (unsigned*)(sm + 3 * NPTS);   // [2][16]
        unsigned* swn = swd + 32;

        const int b    = blockIdx.x;
        const int lane = tid & 31;
        const int warp = tid >> 5;
        const float* pb = pts + b * 3 * NPTS;

        float xs[8], ys[8], zs[8], dist[8];
#pragma unroll
        for (int i = 0; i < 8; i++) {
            int n = tid + i * 512;
            xs[i] = pb[n]; ys[i] = pb[NPTS + n]; zs[i] = pb[2 * NPTS + n];
            spx[n] = xs[i]; spy[n] = ys[i]; spz[n] = zs[i];
            dist[i] = 1e10f;
        }
        u64 X[4], Y[4], Z[4];
#pragma unroll
        for (int j = 0; j < 4; j++) {
            PK2(X[j], xs[2 * j], xs[2 * j + 1]);
            PK2(Y[j], ys[2 * j], ys[2 * j + 1]);
            PK2(Z[j], zs[2 * j], zs[2 * j + 1]);
        }
        __syncthreads();

        float cx = spx[0], cy = spy[0], cz = spz[0];
        float* centb = cent_out + b * 3 * MCENT;
        if (tid == 0) { centb[0] = cx; centb[MCENT] = cy; centb[2 * MCENT] = cz; }

        int p = 0;
        for (int m = 1; m < MCENT; m++) {
            float ncx = -cx, ncy = -cy, ncz = -cz;
            u64 ncx2, ncy2, ncz2;
            PK2(ncx2, ncx, ncx); PK2(ncy2, ncy, ncy); PK2(ncz2, ncz, ncz);
#pragma unroll
            for (int j = 0; j < 4; j++) {
                u64 dx, dy, dz, t;
                ADD2(dx, X[j], ncx2);
                MUL2(t, dx, dx);
                ADD2(dy, Y[j], ncy2);
                FMA2(t, dy, dy, t);
                ADD2(dz, Z[j], ncz2);
                FMA2(t, dz, dz, t);
                float lo, hi; UPK2(lo, hi, t);
                dist[2 * j]     = fminf(dist[2 * j], lo);
                dist[2 * j + 1] = fminf(dist[2 * j + 1], hi);
            }
            float bd = dist[0]; int bi = 0;
#pragma unroll
            for (int i = 1; i < 8; i++) if (dist[i] > bd) { bd = dist[i]; bi = i; }
            unsigned bn = (unsigned)(tid + bi * 512);
            unsigned du = __float_as_uint(bd);
            unsigned wm = __reduce_max_sync(0xffffffffu, du);
            unsigned cd = (du == wm) ? bn : 0xffffffffu;
            unsigned wi = __reduce_min_sync(0xffffffffu, cd);
            if (lane == 0) { swd[p * 16 + warp] = wm; swn[p * 16 + warp] = wi; }
            __syncthreads();
            unsigned kd = (lane < 16) ? swd[p * 16 + lane] : 0u;
            unsigned kn = (lane < 16) ? swn[p * 16 + lane] : 0xffffffffu;
            unsigned gm = __reduce_max_sync(0xffffffffu, kd);
            unsigned c2 = (kd == gm) ? kn : 0xffffffffu;
            unsigned n  = __reduce_min_sync(0xffffffffu, c2);
            cx = spx[n]; cy = spy[n]; cz = spz[n];
            if (tid == 0) {
                centb[m] = cx; centb[MCENT + m] = cy; centb[2 * MCENT + m] = cz;
                if ((m & 3) == 3)   // publish every 4 centroids (release store)
                    asm volatile("st.release.gpu.global.u32 [%0], %1;"
                                 :: "l"(g_prog + b), "r"((unsigned)(m + 1)) : "memory");
            }
            p ^= 1;
        }
        __syncthreads();   // points smem dead; safe to overwrite with weights
    } else if (blockIdx.x < BATCH + 128) {
        // =================== pf slice (first 128 workers) ==================
        float* w1s = sm;            // [c][o] 64*64
        float* b1s = sm + 4096;
        for (int i = tid; i < 64 * 64; i += 512) {
            int c = i >> 6, o = i & 63;
            w1s[i] = w1[o * 67 + 3 + c];
        }
        if (tid < 64) b1s[tid] = b1[tid];
        __syncthreads();

        int bi = blockIdx.x - BATCH;          // 0..127
        int b  = bi >> 3;
        int n  = (bi & 7) * 512 + tid;
        const float* fb = feats + b * CH * NPTS + n;

        float acc[64];
#pragma unroll
        for (int o = 0; o < 64; o++) acc[o] = b1s[o];
#pragma unroll 4
        for (int c = 0; c < 64; c++) {
            float f = fb[c * NPTS];
#pragma unroll
            for (int o = 0; o < 64; o += 4) {
                float4 w = *(const float4*)&w1s[(c << 6) + o];
                acc[o]     = fmaf(w.x, f, acc[o]);
                acc[o + 1] = fmaf(w.y, f, acc[o + 1]);
                acc[o + 2] = fmaf(w.z, f, acc[o + 2]);
                acc[o + 3] = fmaf(w.w, f, acc[o + 3]);
            }
        }
        float* dst = g_pf + (b * NPTS + n) * 64;
#pragma unroll
        for (int o = 0; o < 64; o += 4)
            *(float4*)(dst + o) = make_float4(acc[o], acc[o + 1], acc[o + 2], acc[o + 3]);
        __threadfence();
        __syncthreads();                      // w1s reads done; pf stores visible
        if (tid == 0) atomicAdd(&g_pfdone, 1u);
    }

    // =================== common persistent worker section ==================
    {
        float* w2s  = sm + SMW_W2;
        float* w3s  = sm + SMW_W3;
        float* w1ps = sm + SMW_W1P;
        float* s1   = sm + SMW_S1;
        float* be1s = sm + SMW_BE1;
        float* b2s  = sm + SMW_B2;
        float* s2   = sm + SMW_S2;
        float* be2s = sm + SMW_BE2;
        float* b3s  = sm + SMW_B3;
        float* s3   = sm + SMW_S3;
        float* be3s = sm + SMW_BE3;

        const int q    = tid >> 7;                    // quarter 0..3
        const int qtid = tid & 127;
        const float rs = rsqrtf(1.0f + 1e-5f);

        float*    bufA  = sm + SMW_END + q * QSZ;     // 8704 (swizzled)
        float*    loc   = bufA + 8704;                // [3][128]
        float*    centv = loc + 384;                  // [4][3] (+pad)
        int*      outb  = (int*)(centv + 16);         // [4][128]
        int*      ni_q  = outb + 512;                 // [4][32]
        unsigned* tick  = (unsigned*)(ni_q + 128);    // quarter ticket slot

        // one-time weight load (block-wide; overwrites role-phase smem)
        for (int k = tid; k < 4096; k += 512) { int c = k >> 6, o = k & 63;  w2s[k] = w2[o * 64 + c]; }
        for (int k = tid; k < 8192; k += 512) { int c = k >> 7, o = k & 127; w3s[k] = w3[o * 64 + c]; }
        if (tid < 192) { int d = tid >> 6, o = tid & 63; w1ps[tid] = w1[o * 67 + d]; }
        if (tid < 64) {
            s1[tid] = g1[tid] * rs; be1s[tid] = be1[tid];
            b2s[tid] = b2[tid]; s2[tid] = g2[tid] * rs; be2s[tid] = be2[tid];
        }
        if (tid < 128) { b3s[tid] = b3[tid]; s3[tid] = g3[tid] * rs; be3s[tid] = be3[tid]; }
        __syncthreads();

        // one-time pf gate (per quarter)
        if (qtid == 0) { while (ldacq(&g_pfdone) < 128u) __nanosleep(256); }
        QBAR(q);

        const int rt = qtid >> 3, ct = qtid & 7;
        const int r0 = rt * 8, o0 = ct * 8;
        const int sw = rt & 3;
        const int lane = qtid & 31, wq = qtid >> 5;

        for (;;) {
            if (qtid == 0) tick[0] = atomicAdd(&g_ticket, 1u);
            QBAR(q);
            const unsigned t = tick[0];
            if (t >= NITEMS) break;
            const int b  = (int)(t & 15u);
            const int m0 = (int)((t >> 4) << 2);
            const float* pb = pts + b * 3 * NPTS;

            for (int k = qtid; k < 512; k += 128) outb[k] = 0;
            if (qtid == 0) {
                while (ldacq(&g_prog[b]) < (unsigned)(m0 + 4)) __nanosleep(128);
            }
            QBAR(q);
            if (qtid < 12)   // centroid coords via L2 (L1 may hold a stale line)
                centv[qtid] = __ldcg(cent_out + b * 3 * MCENT + (qtid % 3) * MCENT + m0 + qtid / 3);
            QBAR(q);

            // ball query: warp wq -> centroid wq, 64 pts/iter (dual ballot)
            {
                float cx = centv[wq * 3], cy = centv[wq * 3 + 1], cz = centv[wq * 3 + 2];
                float c2 = cx * cx + cy * cy + cz * cz;
                int* nis = ni_q + wq * 32;
                int cnt = 0, first = -1;
                const unsigned below = (1u << lane) - 1u;
                for (int base = 0; base < NPTS; base += 64) {
                    int n0 = base + 2 * lane;
                    float2 x2 = *(const float2*)(pb + n0);
                    float2 y2 = *(const float2*)(pb + NPTS + n0);
                    float2 z2 = *(const float2*)(pb + 2 * NPTS + n0);
                    float d2a = c2 + (x2.x * x2.x + y2.x * y2.x + z2.x * z2.x)
                              - 2.f * (cx * x2.x + cy * y2.x + cz * z2.x);
                    float d2b = c2 + (x2.y * x2.y + y2.y * y2.y + z2.y * z2.y)
                              - 2.f * (cx * x2.y + cy * y2.y + cz * z2.y);
                    bool h0 = (d2a <= RAD2), h1 = (d2b <= RAD2);
                    unsigned mE = __ballot_sync(0xffffffffu, h0);
                    unsigned mO = __ballot_sync(0xffffffffu, h1);
                    if (mE | mO) {
                        if (first < 0) {
                            int fe = mE ? 2 * (__ffs(mE) - 1)     : 0x7fff;
                            int fo = mO ? 2 * (__ffs(mO) - 1) + 1 : 0x7fff;
                            first = base + min(fe, fo);
                        }
                        if (h0) {
                            int r = cnt + __popc(mE & below) + __popc(mO & below);
                            if (r < KNB) nis[r] = n0;
                        }
                        if (h1) {
                            int r = cnt + __popc(mE & (below | (1u << lane))) + __popc(mO & below);
                            if (r < KNB) nis[r] = n0 + 1;
                        }
                        cnt += __popc(mE) + __popc(mO);
                        if (cnt >= KNB) break;
                    }
                }
                if (cnt < KNB) {
                    int f = (first < 0) ? (NPTS - 1) : first;
                    for (int s = cnt + lane; s < KNB; s += 32) nis[s] = f;
                }
            }
            QBAR(q);

            // gather: warp wq -> group wq rows
            {
                float cx = centv[wq * 3], cy = centv[wq * 3 + 1], cz = centv[wq * 3 + 2];
                int nk = ni_q[wq * 32 + lane];
#pragma unroll 4
                for (int k = 0; k < KNB; k++) {
                    int n = __shfl_sync(0xffffffffu, nk, k);
                    int r = wq * 32 + k;
                    if (lane == 0) {
                        loc[r]       = pb[n] - cx;
                        loc[128 + r] = pb[NPTS + n] - cy;
                        loc[256 + r] = pb[2 * NPTS + n] - cz;
                    }
                    float2 v = *(const float2*)(g_pf + (b * NPTS + n) * 64 + lane * 2);
                    *(float2*)(bufA + aidx(r, lane >> 1) + ((lane & 1) << 1)) = v;
                }
            }
            QBAR(q);

            // layer 1: in place in bufA
            {
                const int r = qtid;
                float lx = loc[r], ly = loc[128 + r], lz = loc[256 + r];
#pragma unroll
                for (int o = 0; o < 64; o += 4) {
                    float* ap = bufA + aidx(r, o >> 2);
                    float4 p  = *(float4*)ap;
                    float4 wx = *(const float4*)(w1ps + o);
                    float4 wy = *(const float4*)(w1ps + 64 + o);
                    float4 wz = *(const float4*)(w1ps + 128 + o);
                    float4 sc = *(const float4*)(s1 + o);
                    float4 eb = *(const float4*)(be1s + o);
                    p.x = fmaf(wz.x, lz, fmaf(wy.x, ly, fmaf(wx.x, lx, p.x)));
                    p.y = fmaf(wz.y, lz, fmaf(wy.y, ly, fmaf(wx.y, lx, p.y)));
                    p.z = fmaf(wz.z, lz, fmaf(wy.z, ly, fmaf(wx.z, lx, p.z)));
                    p.w = fmaf(wz.w, lz, fmaf(wy.w, ly, fmaf(wx.w, lx, p.w)));
                    p.x = fmaxf(fmaf(p.x, sc.x, eb.x), 0.f);
                    p.y = fmaxf(fmaf(p.y, sc.y, eb.y), 0.f);
                    p.z = fmaxf(fmaf(p.z, sc.z, eb.z), 0.f);
                    p.w = fmaxf(fmaf(p.w, sc.w, eb.w), 0.f);
                    *(float4*)ap = p;
                }
            }
            QBAR(q);

            // layer 2 IN PLACE
            {
                u64 acc[8][4];
                gemm8x8p<64>(bufA, w2s, r0, o0, sw, acc);
                float ac[8][8];
#pragma unroll
                for (int ii = 0; ii < 8; ii++)
#pragma unroll
                    for (int j = 0; j < 4; j++) UPK2(ac[ii][2 * j], ac[ii][2 * j + 1], acc[ii][j]);
                float4 bb0 = *(const float4*)(b2s + o0),  bb1 = *(const float4*)(b2s + o0 + 4);
                float4 ss0 = *(const float4*)(s2 + o0),   ss1 = *(const float4*)(s2 + o0 + 4);
                float4 ee0 = *(const float4*)(be2s + o0), ee1 = *(const float4*)(be2s + o0 + 4);
#pragma unroll
                for (int ii = 0; ii < 8; ii++) {
                    ac[ii][0] = fmaxf(fmaf(ac[ii][0] + bb0.x, ss0.x, ee0.x), 0.f);
                    ac[ii][1] = fmaxf(fmaf(ac[ii][1] + bb0.y, ss0.y, ee0.y), 0.f);
                    ac[ii][2] = fmaxf(fmaf(ac[ii][2] + bb0.z, ss0.z, ee0.z), 0.f);
                    ac[ii][3] = fmaxf(fmaf(ac[ii][3] + bb0.w, ss0.w, ee0.w), 0.f);
                    ac[ii][4] = fmaxf(fmaf(ac[ii][4] + bb1.x, ss1.x, ee1.x), 0.f);
                    ac[ii][5] = fmaxf(fmaf(ac[ii][5] + bb1.y, ss1.y, ee1.y), 0.f);
                    ac[ii][6] = fmaxf(fmaf(ac[ii][6] + bb1.z, ss1.z, ee1.z), 0.f);
                    ac[ii][7] = fmaxf(fmaf(ac[ii][7] + bb1.w, ss1.w, ee1.w), 0.f);
                }
                QBAR(q);   // all gemm reads of bufA complete
                const int c4a = o0 >> 2;
#pragma unroll
                for (int ii = 0; ii < 8; ii++) {
                    *(float4*)(bufA + aidx(r0 + ii, c4a)) =
                        make_float4(ac[ii][0], ac[ii][1], ac[ii][2], ac[ii][3]);
                    *(float4*)(bufA + aidx(r0 + ii, c4a + 1)) =
                        make_float4(ac[ii][4], ac[ii][5], ac[ii][6], ac[ii][7]);
                }
            }
            QBAR(q);

            // layer 3 (two col passes) + fused maxpool
            const int gg = r0 >> 5;
#pragma unroll 1
            for (int pp = 0; pp < 2; pp++) {
                const int q0 = o0 + pp * 64;
                u64 acc[8][4];
                gemm8x8p<128>(bufA, w3s, r0, q0, sw, acc);
                float ac[8][8];
#pragma unroll
                for (int ii = 0; ii < 8; ii++)
#pragma unroll
                    for (int j = 0; j < 4; j++) UPK2(ac[ii][2 * j], ac[ii][2 * j + 1], acc[ii][j]);
                float4 bb0 = *(const float4*)(b3s + q0),  bb1 = *(const float4*)(b3s + q0 + 4);
                float4 ss0 = *(const float4*)(s3 + q0),   ss1 = *(const float4*)(s3 + q0 + 4);
                float4 ee0 = *(const float4*)(be3s + q0), ee1 = *(const float4*)(be3s + q0 + 4);
                float cm[8];
#pragma unroll
                for (int j = 0; j < 8; j++) cm[j] = 0.f;
#pragma unroll
                for (int ii = 0; ii < 8; ii++) {
                    cm[0] = fmaxf(cm[0], fmaxf(fmaf(ac[ii][0] + bb0.x, ss0.x, ee0.x), 0.f));
                    cm[1] = fmaxf(cm[1], fmaxf(fmaf(ac[ii][1] + bb0.y, ss0.y, ee0.y), 0.f));
                    cm[2] = fmaxf(cm[2], fmaxf(fmaf(ac[ii][2] + bb0.z, ss0.z, ee0.z), 0.f));
                    cm[3] = fmaxf(cm[3], fmaxf(fmaf(ac[ii][3] + bb0.w, ss0.w, ee0.w), 0.f));
                    cm[4] = fmaxf(cm[4], fmaxf(fmaf(ac[ii][4] + bb1.x, ss1.x, ee1.x), 0.f));
                    cm[5] = fmaxf(cm[5], fmaxf(fmaf(ac[ii][5] + bb1.y, ss1.y, ee1.y), 0.f));
                    cm[6] = fmaxf(cm[6], fmaxf(fmaf(ac[ii][6] + bb1.z, ss1.z, ee1.z), 0.f));
                    cm[7] = fmaxf(cm[7], fmaxf(fmaf(ac[ii][7] + bb1.w, ss1.w, ee1.w), 0.f));
                }
#pragma unroll
                for (int j = 0; j < 8; j++)
                    atomicMax(&outb[gg * 128 + q0 + j], __float_as_int(cm[j]));
            }
            QBAR(q);

            // write out[b][o][m0..m0+3]
            {
                int o = qtid;
                float4 v;
                v.x = __int_as_float(outb[0 * 128 + o]);
                v.y = __int_as_float(outb[1 * 128 + o]);
                v.z = __int_as_float(outb[2 * 128 + o]);
                v.w = __int_as_float(outb[3 * 128 + o]);
                *(float4*)(out + (b * 128 + o) * MCENT + m0) = v;
            }
            QBAR(q);   // outb/bufA/ticket safe to reuse next item
        }
    }
}

// ---------------------------------------------------------------------------
extern "C" void kernel_launch(void* const* d_in, const int* in_sizes, int n_in,
                              void* d_out, int out_size) {
    const float* points   = (const float*)d_in[0];
    const float* features = (const float*)d_in[1];
    const float* w1  = (const float*)d_in[2];
    const float* b1  = (const float*)d_in[3];
    const float* g1  = (const float*)d_in[4];
    const float* be1 = (const float*)d_in[5];
    const float* w2  = (const float*)d_in[6];
    const float* b2  = (const float*)d_in[7];
    const float* g2  = (const float*)d_in[8];
    const float* be2 = (const float*)d_in[9];
    const float* w3  = (const float*)d_in[10];
    const float* b3  = (const float*)d_in[11];
    const float* g3  = (const float*)d_in[12];
    const float* be3 = (const float*)d_in[13];

    float* cent_out = (float*)d_out;                       // [B][3][M]
    float* out      = cent_out + BATCH * 3 * MCENT;        // [B][128][M]

    cudaFuncSetAttribute(mega_kernel, cudaFuncAttributeMaxDynamicSharedMemorySize, MEGA_SMEM);

    init_kernel<<<1, 32>>>();
    mega_kernel<<<BATCH + 132, 512, MEGA_SMEM>>>(
        points, features, w1, b1, g1, be1, w2, b2, g2, be2, w3, b3, g3, be3,
        cent_out, out);
}